// round 17
// baseline (speedup 1.0000x reference)
#include <cuda_runtime.h>
#include <math.h>

#define SS 4096
#define VV 2048
#define BB 8
#define LL 32
#define WW 8
#define ZP 16
#define HS 2048      // states per CTA in the 2-CTA-cluster forward kernel
#define HSTRIDE 520  // halo slot stride floats (512 plane + 4 cw + pad) = 2080 B
#define HBYTES 2080  // bulk-copy size per slot

// Scratch (no allocation allowed in kernel_launch)
__device__ float g_lse[SS];
__device__ float g_prior[SS];
__device__ float g_logp[SS * 7];
__device__ float g_smt[(size_t)VV * SS];   // transposed smoothed emissions: [v][s]
__device__ float g_emis[LL * BB * SS];     // all_emis, layout (l, b, s)

// Order-preserving float <-> uint key (for REDUX.UMAX warp reduction)
__device__ __forceinline__ unsigned f2key(float f) {
    unsigned u = __float_as_uint(f);
    return u ^ (unsigned)(((int)u >> 31) | 0x80000000);
}
__device__ __forceinline__ float key2f(unsigned k) {
    unsigned u = (k & 0x80000000u) ? (k ^ 0x80000000u) : ~k;
    return __uint_as_float(u);
}

__device__ __forceinline__ unsigned smem_u32(const void* p) {
    return (unsigned)__cvta_generic_to_shared(p);
}
__device__ __forceinline__ unsigned mapa_peer(unsigned laddr, unsigned rank) {
    unsigned r;
    asm("mapa.shared::cluster.u32 %0, %1, %2;" : "=r"(r) : "r"(laddr), "r"(rank));
    return r;
}
// One-shot mbarrier wait, parity 0 (HW-sleep try_wait loop)
__device__ __forceinline__ void mbar_wait0(unsigned mb) {
    unsigned done = 0;
    while (!done) {
        asm volatile(
            "{\n\t.reg .pred p;\n\t"
            "mbarrier.try_wait.parity.acquire.cta.shared::cta.b64 p, [%1], 0, 0x989680;\n\t"
            "selp.b32 %0, 1, 0, p;\n\t}"
            : "=r"(done) : "r"(mb) : "memory");
    }
}

// ---------------------------------------------------------------------------
// K_pre fused (512 threads/block):
//   block 0        : prior log_softmax (8 elems/thread)
//   blocks 1..8    : transition logp (512 states/block)
//   blocks 9..264  : row-lse of emis_w (16 warps -> 16 rows/block, 256 blocks)
// ---------------------------------------------------------------------------
__global__ __launch_bounds__(512) void k_pre(const float* __restrict__ pw,
                                             const float* __restrict__ tw,
                                             const float* __restrict__ ew) {
    int bid = blockIdx.x;
    if (bid == 0) {
        __shared__ float red[16];
        __shared__ float bval;
        int tid = threadIdx.x;
        float v[8];
#pragma unroll
        for (int i = 0; i < 8; i++) v[i] = pw[tid + i * 512];
        float m = v[0];
#pragma unroll
        for (int i = 1; i < 8; i++) m = fmaxf(m, v[i]);
#pragma unroll
        for (int o = 16; o; o >>= 1) m = fmaxf(m, __shfl_xor_sync(0xffffffffu, m, o));
        if ((tid & 31) == 0) red[tid >> 5] = m;
        __syncthreads();
        if (tid < 16) {
            float t = red[tid];
#pragma unroll
            for (int o = 8; o; o >>= 1) t = fmaxf(t, __shfl_xor_sync(0xffffu, t, o));
            if (tid == 0) bval = t;
        }
        __syncthreads();
        m = bval;
        float s = 0.f;
#pragma unroll
        for (int i = 0; i < 8; i++) s += __expf(v[i] - m);
#pragma unroll
        for (int o = 16; o; o >>= 1) s += __shfl_xor_sync(0xffffffffu, s, o);
        if ((tid & 31) == 0) red[tid >> 5] = s;
        __syncthreads();
        if (tid < 16) {
            float t = red[tid];
#pragma unroll
            for (int o = 8; o; o >>= 1) t += __shfl_xor_sync(0xffffu, t, o);
            if (tid == 0) bval = t;
        }
        __syncthreads();
        float lse = m + __logf(bval);
#pragma unroll
        for (int i = 0; i < 8; i++) g_prior[tid + i * 512] = v[i] - lse;
    } else if (bid <= 8) {
        int j = (bid - 1) * 512 + threadIdx.x;
        int x = j & 15, y = (j >> 4) & 15, z = j >> 8;
        int v1 = (x < 15), v2 = (x > 0), v3 = (y < 15), v4 = (y > 0), v5 = (z < 15), v6 = (z < 14);
        int nv = 1 + v1 + v2 + v3 + v4 + v5 + v6;
        float w[7];
#pragma unroll
        for (int k = 0; k < 7; k++) w[k] = tw[j * 7 + k];
        float m = w[0];
#pragma unroll
        for (int k = 1; k < 7; k++) if (k < nv) m = fmaxf(m, w[k]);
        float s = 0.f;
#pragma unroll
        for (int k = 0; k < 7; k++) if (k < nv) s += __expf(w[k] - m);
        float lse = m + __logf(s);
        int p2 = 1 + v1;
        int p3 = p2 + v2;
        int p4 = p3 + v3;
        int p5 = p4 + v4;
        int p6 = p5 + v5;
        float* o = g_logp + j * 7;
        o[0] = w[0] - lse;
        o[1] = v1 ? w[1]  - lse : -1e30f;
        o[2] = v2 ? w[p2] - lse : -1e30f;
        o[3] = v3 ? w[p3] - lse : -1e30f;
        o[4] = v4 ? w[p4] - lse : -1e30f;
        o[5] = v5 ? w[p5] - lse : -1e30f;
        o[6] = v6 ? w[p6] - lse : -1e30f;
    } else {
        int row  = (bid - 9) * 16 + (threadIdx.x >> 5);
        int lane = threadIdx.x & 31;
        const float4* r = (const float4*)(ew + (size_t)row * VV);
        float4 v[16];
#pragma unroll
        for (int i = 0; i < 16; i++) v[i] = r[lane + 32 * i];
        float m = -1e30f;
#pragma unroll
        for (int i = 0; i < 16; i++)
            m = fmaxf(m, fmaxf(fmaxf(v[i].x, v[i].y), fmaxf(v[i].z, v[i].w)));
#pragma unroll
        for (int o = 16; o; o >>= 1) m = fmaxf(m, __shfl_xor_sync(0xffffffffu, m, o));
        float s = 0.f;
#pragma unroll
        for (int i = 0; i < 16; i++)
            s += __expf(v[i].x - m) + __expf(v[i].y - m)
               + __expf(v[i].z - m) + __expf(v[i].w - m);
#pragma unroll
        for (int o = 16; o; o >>= 1) s += __shfl_xor_sync(0xffffffffu, s, o);
        if (lane == 0) g_lse[row] = m + __logf(s);
    }
}

// ---------------------------------------------------------------------------
// K2: smoothed emissions, stored TRANSPOSED (SMT[v][s]). (unchanged, proven)
// ---------------------------------------------------------------------------
__global__ __launch_bounds__(512) void k_smt(const float* __restrict__ ew) {
    extern __shared__ float P[];          // 256*67 floats = 68608 B
    __shared__ float slse[256];
    int tx = threadIdx.x & 31;
    int ty = threadIdx.x >> 5;            // 0..15
    int v0 = blockIdx.x * 64;
    int sbase = blockIdx.y * 256;         // z-plane

    if (threadIdx.x < 256) slse[threadIdx.x] = g_lse[sbase + threadIdx.x];
    __syncthreads();

#pragma unroll
    for (int i = 0; i < 16; i++) {
        int sl = ty + 16 * i;
        float l = slse[sl];
        const float* row = ew + (size_t)(sbase + sl) * VV + v0;
        P[sl * 67 + tx]      = __expf(row[tx]      - l);
        P[sl * 67 + 32 + tx] = __expf(row[32 + tx] - l);
    }
    __syncthreads();

#pragma unroll
    for (int jb = 0; jb < 8; jb++) {
        int sl = jb * 32 + tx;
        int x = sl & 15, y = sl >> 4;
        int sxp = sl + (x < 15);
        int sxm = sl - (x > 0);
        int syp = sl + ((y < 15) ? 16 : 0);
        int sym = sl - ((y > 0)  ? 16 : 0);
#pragma unroll
        for (int k = 0; k < 4; k++) {
            int vl = ty + 16 * k;          // 0..63
            float q = P[sl * 67 + vl] + P[sxp * 67 + vl] + P[sxm * 67 + vl]
                    + P[syp * 67 + vl] + P[sym * 67 + vl];
            g_smt[(size_t)(v0 + vl) * SS + sbase + sl] = __logf(q * 0.2f);
        }
    }
}

// ---------------------------------------------------------------------------
// K3: all_emis, float4-vectorized (4 states/thread)
// ---------------------------------------------------------------------------
__global__ void k_emis(const int* __restrict__ stories) {
    __shared__ int tk[WW];
    int s4 = blockIdx.x * 256 + threadIdx.x;   // float4 index (0..1023)
    int lb = blockIdx.y;                       // lb = l*8 + b
    int l = lb >> 3, b = lb & 7;
    if (threadIdx.x < WW) tk[threadIdx.x] = stories[(b * LL + l) * WW + threadIdx.x];
    __syncthreads();
    float4 acc = make_float4(0.f, 0.f, 0.f, 0.f);
#pragma unroll
    for (int w = 0; w < WW; w++) {
        int t = tk[w];
        if (t < VV) {
            float4 v = ((const float4*)(g_smt + (size_t)t * SS))[s4];
            acc.x += v.x; acc.y += v.y; acc.z += v.z; acc.w += v.w;
        }
    }
    ((float4*)g_emis)[(size_t)lb * (SS / 4) + s4] = acc;
}

// ---------------------------------------------------------------------------
// K4: forward recurrence on 2-CTA clusters. One cp.async.bulk per step into
// a full-depth ring with one-shot mbarriers (producer never waits).
// R16+ scheduling changes:
//  * EARLY PUSH: rank1 warps 0-3 stage + named-barrier(128) + bulk copy
//    BEFORE the full __syncthreads, issuing the copy ~400cyc earlier.
//  * LATE WAIT: rank0's halo warps (12-15) accumulate the five local
//    stencil terms first, THEN try_wait, then add the two z-halo terms —
//    overlapping the copy latency with useful work.
// ---------------------------------------------------------------------------
__global__ __launch_bounds__(512, 1) __cluster_dims__(2, 1, 1)
void k_fwd(float* __restrict__ out) {
    // dynamic smem: pbuf[2][HS] then halo[32][HSTRIDE]
    extern __shared__ float dyn[];
    float* pbufs = dyn;                 // 2*HS floats
    float* halo  = dyn + 2 * HS;        // 32*HSTRIDE floats (slot 0 unused)
    __shared__ float cbuf[2][16];
    __shared__ __align__(8) unsigned long long mb[LL];   // one-shot barriers (rank0)

    int tid = threadIdx.x;
    int wid = tid >> 5, lane = tid & 31;
    unsigned rank;
    asm("mov.u32 %0, %%cluster_ctarank;" : "=r"(rank));
    unsigned peer = rank ^ 1u;
    int b   = blockIdx.x >> 1;
    int j0l = tid * 4;                 // local state (0..2044)
    int jg  = (int)rank * HS + j0l;    // global state
    int x0 = jg & 15;
    int y  = (jg >> 4) & 15;

    // Init one-shot mbarriers: count 1 + expect_tx(HBYTES); phase 0 completes
    // exactly when the peer's HBYTES bulk copy lands.
    if (tid == 0) {
#pragma unroll 1
        for (int l = 1; l < LL; l++) {
            unsigned a = smem_u32(&mb[l]);
            asm volatile("mbarrier.init.shared.b64 [%0], 1;" :: "r"(a) : "memory");
            asm volatile("mbarrier.arrive.expect_tx.shared.b64 _, [%0], %1;"
                         :: "r"(a), "r"((unsigned)HBYTES) : "memory");
        }
    }
    __syncthreads();
    asm volatile("barrier.cluster.arrive.aligned;" ::: "memory");
    asm volatile("barrier.cluster.wait.aligned;" ::: "memory");

    unsigned halo_l = smem_u32(halo);
    unsigned halo_r = mapa_peer(halo_l, peer);               // rank1 -> rank0 halo
    unsigned mb0_r  = mapa_peer(smem_u32(&mb[0]), peer);     // peer mb array base

    // Per-state amax + renormalized transition probs (once).
    float Pk[4][7], am[4];
#pragma unroll
    for (int e = 0; e < 4; e++) {
        const float* lp = g_logp + (jg + e) * 7;
        float l[7];
#pragma unroll
        for (int k = 0; k < 7; k++) l[k] = lp[k];
        float m = l[0];
#pragma unroll
        for (int k = 1; k < 7; k++) m = fmaxf(m, l[k]);
        am[e] = m;
#pragma unroll
        for (int k = 0; k < 7; k++) Pk[e][k] = __expf(l[k] - m);  // invalid -> 0
    }

    int wyp = min(wid + 1, 15);
    int wym = max(wid - 1, 0);
    bool edge_hi = (lane >= 28);   // top y-row of this warp's half-plane
    bool edge_lo = (lane < 4);     // bottom y-row
    bool is_pusher = (rank == 1) && (wid < 4);   // stages + sends halo
    bool need_halo = (rank == 0) && (wid >= 12); // consumes halo

    // l = 0: score0 = emis[0,b,:] + prior
    float4 emv = *(const float4*)(g_emis + (size_t)b * SS + jg);
    float4 prv = *(const float4*)(g_prior + jg);
    float sc[4];
    sc[0] = emv.x + prv.x; sc[1] = emv.y + prv.y;
    sc[2] = emv.z + prv.z; sc[3] = emv.w + prv.w;
    *(float4*)(out + (size_t)b * SS + jg) = make_float4(sc[0], sc[1], sc[2], sc[3]);

    float lm = fmaxf(fmaxf(sc[0], sc[1]), fmaxf(sc[2], sc[3]));
    float cw = key2f(__reduce_max_sync(0xffffffffu, f2key(lm)));

    // prefetch emission for l = 1
    float4 emn = *(const float4*)(g_emis + (size_t)(BB + b) * SS + jg);

    int buf = 0;
    for (int l = 1; l < LL; l++) {
        // publish p~ = exp(sc - c_w) and c_w locally
        float4 p;
        p.x = __expf(sc[0] - cw); p.y = __expf(sc[1] - cw);
        p.z = __expf(sc[2] - cw); p.w = __expf(sc[3] - cw);
        float* pb = pbufs + buf * HS;
        *(float4*)(pb + j0l) = p;
        if (lane == 0) cbuf[buf][wid] = cw;

        // EARLY PUSH (rank1 warps 0-3): stage halo slice in OWN slot l,
        // sync just these 128 threads, then one thread issues the bulk copy.
        float* hstage = halo + l * HSTRIDE;
        if (is_pusher) {
            *(float4*)(hstage + j0l) = p;
            if (lane == 0) hstage[512 + wid] = cw;   // wid 0..3
            asm volatile("bar.sync 1, 128;" ::: "memory");
            if (tid == 0) {
                asm volatile("fence.proxy.async.shared::cta;" ::: "memory");
                unsigned dst = halo_r + (unsigned)(l * HSTRIDE) * 4u;
                unsigned src = halo_l + (unsigned)(l * HSTRIDE) * 4u;
                unsigned mbr = mb0_r + (unsigned)l * 8u;
                asm volatile(
                    "cp.async.bulk.shared::cluster.shared::cta.mbarrier::complete_tx::bytes "
                    "[%0], [%1], %2, [%3];"
                    :: "r"(dst), "r"(src), "r"((unsigned)HBYTES), "r"(mbr) : "memory");
            }
        }

        float emr[4] = {emn.x + am[0], emn.y + am[1], emn.z + am[2], emn.w + am[3]};
        if (l + 1 < LL)
            emn = *(const float4*)(g_emis + (size_t)((l + 1) * BB + b) * SS + jg);

        __syncthreads();   // own pbuf/cbuf complete

        // ---- local stencil terms (no halo needed) ----
        float ysel = edge_lo ? cbuf[buf][wym] : (edge_hi ? cbuf[buf][wyp] : cw);
        float s_y  = __expf(ysel - cw);

        float cm1 = (x0 > 0)  ? pb[j0l - 1] : p.x;
        float cp4 = (x0 < 12) ? pb[j0l + 4] : p.w;
        float4 yp = (y < 15) ? *(const float4*)(pb + j0l + 16) : p;
        float4 ym = (y > 0)  ? *(const float4*)(pb + j0l - 16) : p;

        float syp_f = edge_hi ? s_y : 1.f;
        float sym_f = edge_lo ? s_y : 1.f;
        yp.x *= syp_f; yp.y *= syp_f; yp.z *= syp_f; yp.w *= syp_f;
        ym.x *= sym_f; ym.y *= sym_f; ym.z *= sym_f; ym.w *= sym_f;

        float pc[4]  = {p.x, p.y, p.z, p.w};
        float pxp[4] = {p.y, p.z, p.w, cp4};
        float pxm[4] = {cm1, p.x, p.y, p.z};
        float pyp[4] = {yp.x, yp.y, yp.z, yp.w};
        float pym[4] = {ym.x, ym.y, ym.z, ym.w};

        float q[4];
#pragma unroll
        for (int e = 0; e < 4; e++) {
            float t = pc[e] * Pk[e][0];
            t = fmaf(pxp[e], Pk[e][1], t);
            t = fmaf(pxm[e], Pk[e][2], t);
            t = fmaf(pyp[e], Pk[e][3], t);
            t = fmaf(pym[e], Pk[e][4], t);
            q[e] = t;
        }

        // ---- z terms (halo warps wait as late as possible) ----
        int izp = j0l + 256, izq = j0l + 512;
        float4 zp, zq;
        float s_zp, s_zq;
        int wzp = wid + 2, wzq = wid + 4;
        if (!need_halo) {
            // fully local (rank1's z>=14 edges carry Pk==0; clamp only avoids OOB)
            zp = (izp < HS) ? *(const float4*)(pb + izp) : p;
            zq = (izq < HS) ? *(const float4*)(pb + izq) : p;
            float czp = (wzp < 16) ? cbuf[buf][wzp] : cw;
            float czq = (wzq < 16) ? cbuf[buf][wzq] : cw;
            s_zp = __expf(czp - cw);
            s_zq = __expf(czq - cw);
        } else {
            mbar_wait0(smem_u32(&mb[l]));   // LATE WAIT (fast path)
            const float* hslot = halo + l * HSTRIDE;
            zp = (izp < HS) ? *(const float4*)(pb + izp)
                            : *(const float4*)(hslot + (izp - HS));
            zq = *(const float4*)(hslot + (izq - HS));   // wid>=12 -> always halo
            float czp = (wzp < 16) ? cbuf[buf][wzp] : hslot[512 + (wzp - 16)];
            float czq = hslot[512 + (wzq - 16)];
            s_zp = __expf(czp - cw);
            s_zq = __expf(czq - cw);
        }
        zp.x *= s_zp; zp.y *= s_zp; zp.z *= s_zp; zp.w *= s_zp;
        zq.x *= s_zq; zq.y *= s_zq; zq.z *= s_zq; zq.w *= s_zq;

        float pzp[4] = {zp.x, zp.y, zp.z, zp.w};
        float pzq[4] = {zq.x, zq.y, zq.z, zq.w};

        float lmn = -1e30f;
#pragma unroll
        for (int e = 0; e < 4; e++) {
            float t = fmaf(pzp[e], Pk[e][5], q[e]);
            t = fmaf(pzq[e], Pk[e][6], t);
            sc[e] = emr[e] + __logf(t) + cw;
            lmn = fmaxf(lmn, sc[e]);
        }
        *(float4*)(out + (size_t)(l * BB + b) * SS + jg) =
            make_float4(sc[0], sc[1], sc[2], sc[3]);

        cw = key2f(__reduce_max_sync(0xffffffffu, f2key(lmn)));
        buf ^= 1;
    }

    // keep SMEM alive until the peer's remote copies/reads are done
    asm volatile("barrier.cluster.arrive.aligned;" ::: "memory");
    asm volatile("barrier.cluster.wait.aligned;" ::: "memory");
}

// ---------------------------------------------------------------------------
extern "C" void kernel_launch(void* const* d_in, const int* in_sizes, int n_in,
                              void* d_out, int out_size) {
    const int*   stories = nullptr;
    const float* trans_w = nullptr;
    const float* emis_w  = nullptr;
    const float* prior_w = nullptr;
    for (int i = 0; i < n_in; i++) {
        switch (in_sizes[i]) {
            case 2048:            stories = (const int*)d_in[i];   break;
            case 28672:           trans_w = (const float*)d_in[i]; break;
            case SS * VV:         emis_w  = (const float*)d_in[i]; break;
            case SS:              prior_w = (const float*)d_in[i]; break;
            default: break;
        }
    }
    float* out = (float*)d_out;

    const int smt_smem = 256 * 67 * sizeof(float);                // 68608 B
    const int fwd_smem = (2 * HS + 32 * HSTRIDE) * sizeof(float); // 82944 B
    cudaFuncSetAttribute(k_smt, cudaFuncAttributeMaxDynamicSharedMemorySize, smt_smem);
    cudaFuncSetAttribute(k_fwd, cudaFuncAttributeMaxDynamicSharedMemorySize, fwd_smem);

    k_pre<<<265, 512>>>(prior_w, trans_w, emis_w);
    k_smt<<<dim3(VV / 64, ZP), 512, smt_smem>>>(emis_w);
    k_emis<<<dim3(SS / 1024, LL * BB), 256>>>(stories);
    k_fwd<<<BB * 2, 512, fwd_smem>>>(out);
    (void)out_size;
}